// round 10
// baseline (speedup 1.0000x reference)
#include <cuda_runtime.h>
#include <cuda_bf16.h>
#include <stdint.h>

#define N_NODES 50000
#define N_EDGES 800000
#define EDGE_F  96
#define NODE_F  256
#define GLOB_F  64
#define HIDDEN  1024
#define MLP_IN  608
#define KH      544   // GEMM1 K: x(256) + sum/max/mean(288); u folded into bias table

// ---------------- scratch (device globals: allocation-free) ----------------
__device__ int g_deg[N_NODES];        // zero at load; fill_kernel re-zeros each run
__device__ int g_off[N_NODES + 1];
__device__ int g_cur[N_NODES];
__device__ int g_bin[N_EDGES];
__device__ float g_ub1[8 * HIDDEN];   // per-graph bias table b1 + u[g] @ W1[544:608]
// tf32-valued f32 operands (pre-rounded with cvt.rna.tf32)
__device__ alignas(16) float g_H[(size_t)N_NODES * KH];
__device__ alignas(16) float g_mid[(size_t)N_NODES * HIDDEN];
__device__ alignas(16) float g_Wt1[(size_t)HIDDEN * KH];      // [n][k]
__device__ alignas(16) float g_Wt2[(size_t)NODE_F * HIDDEN];  // [n][k]

// ======================= helpers ===========================================
__device__ __forceinline__ uint32_t smem_to_u32(const void* p) {
    uint32_t a;
    asm("{ .reg .u64 t; cvta.to.shared.u64 t, %1; cvt.u32.u64 %0, t; }"
        : "=r"(a) : "l"(p));
    return a;
}

__device__ __forceinline__ void cp16(uint32_t dst, const void* src, bool valid) {
    asm volatile("cp.async.cg.shared.global [%0], [%1], 16, %2;"
                 :: "r"(dst), "l"(src), "r"(valid ? 16 : 0));
}
#define CP_COMMIT() asm volatile("cp.async.commit_group;" ::: "memory")
#define CP_WAIT(n)  asm volatile("cp.async.wait_group %0;" :: "n"(n) : "memory")

__device__ __forceinline__ void ldsm4(uint32_t* r, uint32_t addr) {
    asm volatile("ldmatrix.sync.aligned.m8n8.x4.shared.b16 {%0,%1,%2,%3}, [%4];"
                 : "=r"(r[0]), "=r"(r[1]), "=r"(r[2]), "=r"(r[3]) : "r"(addr));
}

// tf32 mma: D[16x8] += A[16x8] * B[8x8]
__device__ __forceinline__ void mma1688(float* d, const uint32_t* a,
                                        uint32_t b0, uint32_t b1) {
    asm volatile(
        "mma.sync.aligned.m16n8k8.row.col.f32.tf32.tf32.f32 "
        "{%0,%1,%2,%3}, {%4,%5,%6,%7}, {%8,%9}, {%0,%1,%2,%3};"
        : "+f"(d[0]), "+f"(d[1]), "+f"(d[2]), "+f"(d[3])
        : "r"(a[0]), "r"(a[1]), "r"(a[2]), "r"(a[3]), "r"(b0), "r"(b1));
}

// round-to-nearest-even into tf32 (low 13 mantissa bits zeroed)
__device__ __forceinline__ float tf32r(float f) {
    uint32_t r;
    asm("cvt.rna.tf32.f32 %0, %1;" : "=r"(r) : "f"(f));
    return __uint_as_float(r);
}

// 128B-row smem tile, 8x 16B chunks, full XOR swizzle (conflict-free ldmatrix)
__device__ __forceinline__ uint32_t sw_off(int row, int chunk) {
    return (uint32_t)row * 128u + (uint32_t)((chunk ^ (row & 7)) << 4);
}

// ===================== CSR build ===========================================
__global__ void count_kernel(const int* __restrict__ col) {
    int e = blockIdx.x * blockDim.x + threadIdx.x;
    if (e < N_EDGES) atomicAdd(&g_deg[col[e]], 1);
}

__global__ void scan_kernel() {
    __shared__ int warp_sums[32];
    __shared__ int carry_s;
    const int tid = threadIdx.x;
    const int lane = tid & 31, wid = tid >> 5;
    if (tid == 0) carry_s = 0;
    __syncthreads();
    for (int base = 0; base < N_NODES; base += 1024) {
        int i = base + tid;
        int v = (i < N_NODES) ? g_deg[i] : 0;
        int x = v;
        #pragma unroll
        for (int o = 1; o < 32; o <<= 1) {
            int y = __shfl_up_sync(0xFFFFFFFFu, x, o);
            if (lane >= o) x += y;
        }
        if (lane == 31) warp_sums[wid] = x;
        __syncthreads();
        if (wid == 0) {
            int w = warp_sums[lane];
            #pragma unroll
            for (int o = 1; o < 32; o <<= 1) {
                int y = __shfl_up_sync(0xFFFFFFFFu, w, o);
                if (lane >= o) w += y;
            }
            warp_sums[lane] = w;
        }
        __syncthreads();
        int excl = x - v + (wid > 0 ? warp_sums[wid - 1] : 0) + carry_s;
        if (i < N_NODES) {
            g_off[i] = excl;
            g_cur[i] = excl;
        }
        __syncthreads();
        if (tid == 0) carry_s += warp_sums[31];
        __syncthreads();
    }
    if (tid == 0) g_off[N_NODES] = N_EDGES;
}

__global__ void fill_kernel(const int* __restrict__ col) {
    int e = blockIdx.x * blockDim.x + threadIdx.x;
    if (e < N_EDGES) {
        int pos = atomicAdd(&g_cur[col[e]], 1);
        g_bin[pos] = e;
    }
    if (e < N_NODES) g_deg[e] = 0;
}

// ============ merged prep: gather | rest(x) | wt1 | wt2 | ub1 ==============
#define G_GATHER 6250                          // 50000 warps, 8/block
#define G_REST   12500                         // 50000*256/4 /256
#define G_WT1    (HIDDEN * (KH / 4) / 256)     // 544
#define G_WT2    (NODE_F * (HIDDEN / 4) / 256) // 256
#define G_UB1    32

__global__ void prep_kernel(const float* __restrict__ edge_attr,
                            const float* __restrict__ x,
                            const float* __restrict__ u,
                            const float* __restrict__ W1,
                            const float* __restrict__ b1,
                            const float* __restrict__ W2) {
    const int b = blockIdx.x;
    if (b < G_GATHER) {
        // ---- gather: warp per node -> H cols [256,544), tf32-rounded ----
        const int warp_g = (b * 256 + (int)threadIdx.x) >> 5;
        if (warp_g >= N_NODES) return;
        const int lane = threadIdx.x & 31;
        const int beg = g_off[warp_g];
        const int end = g_off[warp_g + 1];

        float s0 = 0.f, s1 = 0.f, s2 = 0.f;
        float m0 = -__int_as_float(0x7F800000), m1 = m0, m2 = m0;

        for (int i = beg; i < end; i++) {
            const int e = g_bin[i];
            const float* row = edge_attr + (size_t)e * EDGE_F;
            float v0 = row[lane];
            float v1 = row[lane + 32];
            float v2 = row[lane + 64];
            s0 += v0; s1 += v1; s2 += v2;
            m0 = fmaxf(m0, v0); m1 = fmaxf(m1, v1); m2 = fmaxf(m2, v2);
        }
        const int cnt = end - beg;
        if (cnt == 0) { m0 = 0.f; m1 = 0.f; m2 = 0.f; }
        const float inv = 1.0f / (float)max(cnt, 1);

        float* H = g_H + (size_t)warp_g * KH;
        H[256 + lane] = tf32r(s0);
        H[288 + lane] = tf32r(s1);
        H[320 + lane] = tf32r(s2);
        H[352 + lane] = tf32r(m0);
        H[384 + lane] = tf32r(m1);
        H[416 + lane] = tf32r(m2);
        H[448 + lane] = tf32r(s0 * inv);
        H[480 + lane] = tf32r(s1 * inv);
        H[512 + lane] = tf32r(s2 * inv);
    } else if (b < G_GATHER + G_REST) {
        // ---- rest: H cols [0,256) = tf32(x), float4 ----
        const int t = (b - G_GATHER) * 256 + (int)threadIdx.x;
        const int n = t >> 6;
        const int c = (t & 63) * 4;
        if (n >= N_NODES) return;
        float4 v = *reinterpret_cast<const float4*>(x + (size_t)n * NODE_F + c);
        v.x = tf32r(v.x); v.y = tf32r(v.y); v.z = tf32r(v.z); v.w = tf32r(v.w);
        *reinterpret_cast<float4*>(g_H + (size_t)n * KH + c) = v;
    } else if (b < G_GATHER + G_REST + G_WT1) {
        // ---- wt1: Wt1[n][k] = tf32(W1[k][n]), k in [0,544) ----
        const int t = (b - G_GATHER - G_REST) * 256 + (int)threadIdx.x;
        const int n = t / (KH / 4);
        const int k = (t % (KH / 4)) * 4;
        float4 v;
        v.x = tf32r(W1[(size_t)(k + 0) * HIDDEN + n]);
        v.y = tf32r(W1[(size_t)(k + 1) * HIDDEN + n]);
        v.z = tf32r(W1[(size_t)(k + 2) * HIDDEN + n]);
        v.w = tf32r(W1[(size_t)(k + 3) * HIDDEN + n]);
        *reinterpret_cast<float4*>(g_Wt1 + (size_t)n * KH + k) = v;
    } else if (b < G_GATHER + G_REST + G_WT1 + G_WT2) {
        // ---- wt2: Wt2[n][k] = tf32(W2[k][n]) ----
        const int t = (b - G_GATHER - G_REST - G_WT1) * 256 + (int)threadIdx.x;
        const int n = t / (HIDDEN / 4);
        const int k = (t % (HIDDEN / 4)) * 4;
        float4 v;
        v.x = tf32r(W2[(size_t)(k + 0) * NODE_F + n]);
        v.y = tf32r(W2[(size_t)(k + 1) * NODE_F + n]);
        v.z = tf32r(W2[(size_t)(k + 2) * NODE_F + n]);
        v.w = tf32r(W2[(size_t)(k + 3) * NODE_F + n]);
        *reinterpret_cast<float4*>(g_Wt2 + (size_t)n * HIDDEN + k) = v;
    } else {
        // ---- ub1[g][n] = b1[n] + sum_k u[g,k] * W1[544+k][n]  (full f32) ----
        const int t = (b - G_GATHER - G_REST - G_WT1 - G_WT2) * 256 + (int)threadIdx.x;
        const int g = t >> 10;
        const int n = t & 1023;
        if (g >= 8) return;
        float s = b1[n];
        #pragma unroll 8
        for (int k = 0; k < GLOB_F; k++)
            s = fmaf(u[g * GLOB_F + k], W1[(size_t)(KH + k) * HIDDEN + n], s);
        g_ub1[g * HIDDEN + n] = s;
    }
}

// ================= TF32 GEMM on mma.sync m16n8k8 ===========================
// C[128,128]/CTA, 8 warps 2(M)x4(N), warp tile 64x32, KC=32, S=3, 2 CTAs/SM.
// A: [M][K] tf32-f32 row-major; B: [N][K] tf32-f32 (K contiguous = col-major).
// MODE 0: out = tf32(relu(acc + ub1[batch[row]][col])) -> f32 mid
// MODE 1: out = acc + bias[col] + resid -> f32
template<int K_TOTAL, int N_TOTAL, int MODE>
__global__ void __launch_bounds__(256, 2) tf32_gemm_kernel(
    const float* __restrict__ A, const float* __restrict__ B,
    const float* __restrict__ bias, const float* __restrict__ resid,
    const int* __restrict__ batchp,
    float* __restrict__ outf, int M)
{
    constexpr int KC = 32;
    constexpr int S  = 3;
    constexpr int TILE_B = 128 * 128;     // 16 KB (128 rows x 32 f32)
    constexpr int STAGE_B = 2 * TILE_B;   // A + B
    constexpr int NCH = K_TOTAL / KC;

    extern __shared__ char smem[];
    const uint32_t smem_u = smem_to_u32(smem);

    const int tid = threadIdx.x;
    const int lid = tid & 31;
    const int wid = tid >> 5;
    const int warp_m = wid & 1;
    const int warp_n = wid >> 1;
    const int blockN = blockIdx.x * 128;
    const int blockM = blockIdx.y * 128;

    float acc[64];
    #pragma unroll
    for (int i = 0; i < 64; i++) acc[i] = 0.0f;

    // gmem->smem: 128 rows x 8 chunks(16B); thread -> row tid/2, 4 chunks
    const int ldrow = tid >> 1;
    const int ldcb  = (tid & 1) * 4;

    auto load_chunk = [&](int c) {
        if (c >= NCH) return;
        const int kb = c * KC;
        const uint32_t sb = smem_u + (uint32_t)(c % S) * STAGE_B;
        const int gr = blockM + ldrow;
        const bool v = gr < M;
        const size_t goA = (size_t)(v ? gr : 0) * K_TOTAL + kb;
        const size_t goB = (size_t)(blockN + ldrow) * K_TOTAL + kb;
        #pragma unroll
        for (int i = 0; i < 4; i++) {
            const int ch = ldcb + i;
            const uint32_t doff = sw_off(ldrow, ch);
            cp16(sb + doff, A + goA + ch * 4, v);
            cp16(sb + TILE_B + doff, B + goB + ch * 4, true);
        }
    };

    #pragma unroll
    for (int c = 0; c < S - 1; c++) {
        load_chunk(c);
        CP_COMMIT();
    }

    // ldmatrix lane-address components
    const int a_r = (lid & 7) + (lid & 8);          // row within 16
    const int a_c = (lid >> 4);                     // +chunk
    const int b_r = (lid & 7) + ((lid >> 1) & 8);   // row within 16 (n)
    const int b_c = ((lid >> 3) & 1);               // +chunk

    for (int c = 0; c < NCH; c++) {
        load_chunk(c + S - 1);
        CP_COMMIT();
        CP_WAIT(S - 1);
        __syncthreads();

        const uint32_t sb = smem_u + (uint32_t)(c % S) * STAGE_B;
        const uint32_t aT = sb, bT = sb + TILE_B;

        #pragma unroll
        for (int k8 = 0; k8 < KC; k8 += 8) {
            const int c0 = k8 >> 2;  // 16B chunk index of this k8 (2 chunks)
            // B fragments: octets 0-3 of warp's n=32
            uint32_t bf0[4], bf1[4];
            ldsm4(bf0, bT + sw_off(warp_n * 32 + b_r, c0 + b_c));
            ldsm4(bf1, bT + sw_off(warp_n * 32 + 16 + b_r, c0 + b_c));
            #pragma unroll
            for (int am = 0; am < 4; am++) {
                uint32_t af[4];
                ldsm4(af, aT + sw_off(warp_m * 64 + am * 16 + a_r, c0 + a_c));
                mma1688(&acc[(am * 4 + 0) * 4], af, bf0[0], bf0[1]);
                mma1688(&acc[(am * 4 + 1) * 4], af, bf0[2], bf0[3]);
                mma1688(&acc[(am * 4 + 2) * 4], af, bf1[0], bf1[1]);
                mma1688(&acc[(am * 4 + 3) * 4], af, bf1[2], bf1[3]);
            }
        }
        __syncthreads();
    }

    const int g = lid >> 2;
    const int t = lid & 3;
    #pragma unroll
    for (int am = 0; am < 4; am++) {
        #pragma unroll
        for (int an = 0; an < 4; an++) {
            const float* d = &acc[(am * 4 + an) * 4];
            const int col = blockN + warp_n * 32 + an * 8 + 2 * t;
            #pragma unroll
            for (int half = 0; half < 2; half++) {
                const int row = blockM + warp_m * 64 + am * 16 + g + half * 8;
                if (row >= M) continue;
                float bia0, bia1;
                if (MODE == 0) {
                    const int gg = batchp[row];
                    bia0 = bias[gg * N_TOTAL + col];
                    bia1 = bias[gg * N_TOTAL + col + 1];
                } else {
                    bia0 = bias[col];
                    bia1 = bias[col + 1];
                }
                float v0 = d[half * 2 + 0] + bia0;
                float v1 = d[half * 2 + 1] + bia1;
                const size_t o = (size_t)row * N_TOTAL + col;
                float2 r;
                if (MODE == 0) {
                    r.x = tf32r(fmaxf(v0, 0.0f));
                    r.y = tf32r(fmaxf(v1, 0.0f));
                } else {
                    r.x = v0 + resid[o];
                    r.y = v1 + resid[o + 1];
                }
                *reinterpret_cast<float2*>(outf + o) = r;
            }
        }
    }
}

// ---------------- launch ----------------
extern "C" void kernel_launch(void* const* d_in, const int* in_sizes, int n_in,
                              void* d_out, int out_size) {
    const float* x         = (const float*)d_in[0];
    const float* edge_attr = (const float*)d_in[1];
    const float* u         = (const float*)d_in[2];
    const float* W1        = (const float*)d_in[3];
    const float* b1        = (const float*)d_in[4];
    const float* W2        = (const float*)d_in[5];
    const float* b2        = (const float*)d_in[6];
    const int*   edge_index= (const int*)d_in[7];
    const int*   batch     = (const int*)d_in[8];
    float* out = (float*)d_out;

    const int* col = edge_index + N_EDGES;

    float *pH, *pMid, *pW1, *pW2, *pUb1;
    cudaGetSymbolAddress((void**)&pH,   g_H);
    cudaGetSymbolAddress((void**)&pMid, g_mid);
    cudaGetSymbolAddress((void**)&pW1,  g_Wt1);
    cudaGetSymbolAddress((void**)&pW2,  g_Wt2);
    cudaGetSymbolAddress((void**)&pUb1, g_ub1);

    const int SMEM_BYTES = 3 * 2 * 128 * 128;   // 98304
    cudaFuncSetAttribute(tf32_gemm_kernel<KH, HIDDEN, 0>,
                         cudaFuncAttributeMaxDynamicSharedMemorySize, SMEM_BYTES);
    cudaFuncSetAttribute(tf32_gemm_kernel<HIDDEN, NODE_F, 1>,
                         cudaFuncAttributeMaxDynamicSharedMemorySize, SMEM_BYTES);

    // 1-3) CSR
    count_kernel<<<(N_EDGES + 255) / 256, 256>>>(col);
    scan_kernel<<<1, 1024>>>();
    fill_kernel<<<(N_EDGES + 255) / 256, 256>>>(col);
    // 4) merged prep
    prep_kernel<<<G_GATHER + G_REST + G_WT1 + G_WT2 + G_UB1, 256>>>(
        edge_attr, x, u, W1, b1, W2);
    // 5) GEMM1: mid = tf32(relu(H @ W1[0:544] + ub1[batch]))  [50000,1024]
    {
        dim3 grid(HIDDEN / 128, (N_NODES + 127) / 128);
        tf32_gemm_kernel<KH, HIDDEN, 0><<<grid, 256, SMEM_BYTES>>>(
            pH, pW1, pUb1, nullptr, batch, pMid, N_NODES);
    }
    // 6) GEMM2: out = mid @ W2 + b2 + x  [50000,256]
    {
        dim3 grid(NODE_F / 128, (N_NODES + 127) / 128);
        tf32_gemm_kernel<HIDDEN, NODE_F, 1><<<grid, 256, SMEM_BYTES>>>(
            pMid, pW2, b2, x, nullptr, out, N_NODES);
    }
}

// round 12
// speedup vs baseline: 1.7007x; 1.7007x over previous
#include <cuda_runtime.h>
#include <cuda_fp16.h>
#include <stdint.h>

#define N_NODES 50000
#define N_EDGES 800000
#define EDGE_F  96
#define NODE_F  256
#define GLOB_F  64
#define HIDDEN  1024
#define MLP_IN  608
#define KH      544   // GEMM1 K: x(256) + sum/max/mean(288); u folded into bias table

// ---------------- scratch (device globals: allocation-free) ----------------
__device__ int g_deg[N_NODES];        // zero at load; fill_kernel re-zeros each run
__device__ int g_off[N_NODES + 1];
__device__ int g_cur[N_NODES];
__device__ int g_bin[N_EDGES];
__device__ float g_ub1[8 * HIDDEN];   // per-graph bias: b1 + u[g] @ W1[544:608]
// fp16 operands: activations split hi/lo (exact), weights rounded hi-only
__device__ alignas(16) __half g_Hh[(size_t)N_NODES * KH];
__device__ alignas(16) __half g_Hl[(size_t)N_NODES * KH];
__device__ alignas(16) __half g_midh[(size_t)N_NODES * HIDDEN];
__device__ alignas(16) __half g_midl[(size_t)N_NODES * HIDDEN];
__device__ alignas(16) __half g_Wt1[(size_t)HIDDEN * KH];      // [n][k]
__device__ alignas(16) __half g_Wt2[(size_t)NODE_F * HIDDEN];  // [n][k]

// ======================= helpers ===========================================
__device__ __forceinline__ uint32_t smem_to_u32(const void* p) {
    uint32_t a;
    asm("{ .reg .u64 t; cvta.to.shared.u64 t, %1; cvt.u32.u64 %0, t; }"
        : "=r"(a) : "l"(p));
    return a;
}

__device__ __forceinline__ void cp16(uint32_t dst, const void* src, bool valid) {
    asm volatile("cp.async.cg.shared.global [%0], [%1], 16, %2;"
                 :: "r"(dst), "l"(src), "r"(valid ? 16 : 0));
}
#define CP_COMMIT() asm volatile("cp.async.commit_group;" ::: "memory")
#define CP_WAIT(n)  asm volatile("cp.async.wait_group %0;" :: "n"(n) : "memory")

__device__ __forceinline__ void ldsm4(uint32_t* r, uint32_t addr) {
    asm volatile("ldmatrix.sync.aligned.m8n8.x4.shared.b16 {%0,%1,%2,%3}, [%4];"
                 : "=r"(r[0]), "=r"(r[1]), "=r"(r[2]), "=r"(r[3]) : "r"(addr));
}

// fp16 mma with f32 accumulate: D[16x8] += A[16x16] * B[16x8]
__device__ __forceinline__ void mma16816(float* d, const uint32_t* a,
                                         uint32_t b0, uint32_t b1) {
    asm volatile(
        "mma.sync.aligned.m16n8k16.row.col.f32.f16.f16.f32 "
        "{%0,%1,%2,%3}, {%4,%5,%6,%7}, {%8,%9}, {%0,%1,%2,%3};"
        : "+f"(d[0]), "+f"(d[1]), "+f"(d[2]), "+f"(d[3])
        : "r"(a[0]), "r"(a[1]), "r"(a[2]), "r"(a[3]), "r"(b0), "r"(b1));
}

__device__ __forceinline__ void split_f16(float v, __half& h, __half& l) {
    h = __float2half_rn(v);
    l = __float2half_rn(v - __half2float(h));
}

// 64B-row smem tile with XOR swizzle (conflict-free for 8-lane ldmatrix phases)
__device__ __forceinline__ uint32_t sw_off(int row, int chunk) {
    return (uint32_t)row * 64u + (uint32_t)((chunk ^ ((row >> 1) & 3)) << 4);
}

// ===================== CSR build ===========================================
__global__ void count_kernel(const int* __restrict__ col) {
    int e = blockIdx.x * blockDim.x + threadIdx.x;
    if (e < N_EDGES) atomicAdd(&g_deg[col[e]], 1);
}

__global__ void scan_kernel() {
    __shared__ int warp_sums[32];
    __shared__ int carry_s;
    const int tid = threadIdx.x;
    const int lane = tid & 31, wid = tid >> 5;
    if (tid == 0) carry_s = 0;
    __syncthreads();
    for (int base = 0; base < N_NODES; base += 1024) {
        int i = base + tid;
        int v = (i < N_NODES) ? g_deg[i] : 0;
        int x = v;
        #pragma unroll
        for (int o = 1; o < 32; o <<= 1) {
            int y = __shfl_up_sync(0xFFFFFFFFu, x, o);
            if (lane >= o) x += y;
        }
        if (lane == 31) warp_sums[wid] = x;
        __syncthreads();
        if (wid == 0) {
            int w = warp_sums[lane];
            #pragma unroll
            for (int o = 1; o < 32; o <<= 1) {
                int y = __shfl_up_sync(0xFFFFFFFFu, w, o);
                if (lane >= o) w += y;
            }
            warp_sums[lane] = w;
        }
        __syncthreads();
        int excl = x - v + (wid > 0 ? warp_sums[wid - 1] : 0) + carry_s;
        if (i < N_NODES) {
            g_off[i] = excl;
            g_cur[i] = excl;
        }
        __syncthreads();
        if (tid == 0) carry_s += warp_sums[31];
        __syncthreads();
    }
    if (tid == 0) g_off[N_NODES] = N_EDGES;
}

__global__ void fill_kernel(const int* __restrict__ col) {
    int e = blockIdx.x * blockDim.x + threadIdx.x;
    if (e < N_EDGES) {
        int pos = atomicAdd(&g_cur[col[e]], 1);
        g_bin[pos] = e;
    }
    if (e < N_NODES) g_deg[e] = 0;
}

// ============ merged prep: gather | rest(x) | wt1 | wt2 | ub1 ==============
#define G_GATHER 6250                          // 50000 warps, 8/block
#define G_REST   12500                         // 50000*256/4 /256
#define G_WT1    (HIDDEN * (KH / 4) / 256)     // 544
#define G_WT2    (NODE_F * (HIDDEN / 4) / 256) // 256
#define G_UB1    32

__global__ void prep_kernel(const float* __restrict__ edge_attr,
                            const float* __restrict__ x,
                            const float* __restrict__ u,
                            const float* __restrict__ W1,
                            const float* __restrict__ b1,
                            const float* __restrict__ W2) {
    const int b = blockIdx.x;
    if (b < G_GATHER) {
        // ---- gather: warp per node -> H cols [256,544), fp16 split ----
        const int warp_g = (b * 256 + (int)threadIdx.x) >> 5;
        if (warp_g >= N_NODES) return;
        const int lane = threadIdx.x & 31;
        const int beg = g_off[warp_g];
        const int end = g_off[warp_g + 1];

        float s0 = 0.f, s1 = 0.f, s2 = 0.f;
        float m0 = -__int_as_float(0x7F800000), m1 = m0, m2 = m0;

        for (int i = beg; i < end; i++) {
            const int e = g_bin[i];
            const float* row = edge_attr + (size_t)e * EDGE_F;
            float v0 = row[lane];
            float v1 = row[lane + 32];
            float v2 = row[lane + 64];
            s0 += v0; s1 += v1; s2 += v2;
            m0 = fmaxf(m0, v0); m1 = fmaxf(m1, v1); m2 = fmaxf(m2, v2);
        }
        const int cnt = end - beg;
        if (cnt == 0) { m0 = 0.f; m1 = 0.f; m2 = 0.f; }
        const float inv = 1.0f / (float)max(cnt, 1);

        const size_t rb = (size_t)warp_g * KH;
        __half h, l;
        split_f16(s0, h, l); g_Hh[rb + 256 + lane] = h; g_Hl[rb + 256 + lane] = l;
        split_f16(s1, h, l); g_Hh[rb + 288 + lane] = h; g_Hl[rb + 288 + lane] = l;
        split_f16(s2, h, l); g_Hh[rb + 320 + lane] = h; g_Hl[rb + 320 + lane] = l;
        split_f16(m0, h, l); g_Hh[rb + 352 + lane] = h; g_Hl[rb + 352 + lane] = l;
        split_f16(m1, h, l); g_Hh[rb + 384 + lane] = h; g_Hl[rb + 384 + lane] = l;
        split_f16(m2, h, l); g_Hh[rb + 416 + lane] = h; g_Hl[rb + 416 + lane] = l;
        split_f16(s0 * inv, h, l); g_Hh[rb + 448 + lane] = h; g_Hl[rb + 448 + lane] = l;
        split_f16(s1 * inv, h, l); g_Hh[rb + 480 + lane] = h; g_Hl[rb + 480 + lane] = l;
        split_f16(s2 * inv, h, l); g_Hh[rb + 512 + lane] = h; g_Hl[rb + 512 + lane] = l;
    } else if (b < G_GATHER + G_REST) {
        // ---- rest: H cols [0,256) = x, fp16 split, x4 ----
        const int t = (b - G_GATHER) * 256 + (int)threadIdx.x;
        const int n = t >> 6;
        const int c = (t & 63) * 4;
        if (n >= N_NODES) return;
        const float4 v = *reinterpret_cast<const float4*>(x + (size_t)n * NODE_F + c);
        const size_t o = (size_t)n * KH + c;
        __half h0, l0, h1, l1, h2, l2, h3, l3;
        split_f16(v.x, h0, l0); split_f16(v.y, h1, l1);
        split_f16(v.z, h2, l2); split_f16(v.w, h3, l3);
        __half2 ph0(h0, h1), ph1(h2, h3), pl0(l0, l1), pl1(l2, l3);
        reinterpret_cast<__half2*>(g_Hh + o)[0] = ph0;
        reinterpret_cast<__half2*>(g_Hh + o)[1] = ph1;
        reinterpret_cast<__half2*>(g_Hl + o)[0] = pl0;
        reinterpret_cast<__half2*>(g_Hl + o)[1] = pl1;
    } else if (b < G_GATHER + G_REST + G_WT1) {
        // ---- wt1: Wt1[n][k] = fp16(W1[k][n]), k in [0,544) ----
        const int t = (b - G_GATHER - G_REST) * 256 + (int)threadIdx.x;
        const int n = t / (KH / 4);
        const int k = (t % (KH / 4)) * 4;
        const size_t o = (size_t)n * KH + k;
        __half2 p0(__float2half_rn(W1[(size_t)(k + 0) * HIDDEN + n]),
                   __float2half_rn(W1[(size_t)(k + 1) * HIDDEN + n]));
        __half2 p1(__float2half_rn(W1[(size_t)(k + 2) * HIDDEN + n]),
                   __float2half_rn(W1[(size_t)(k + 3) * HIDDEN + n]));
        reinterpret_cast<__half2*>(g_Wt1 + o)[0] = p0;
        reinterpret_cast<__half2*>(g_Wt1 + o)[1] = p1;
    } else if (b < G_GATHER + G_REST + G_WT1 + G_WT2) {
        // ---- wt2: Wt2[n][k] = fp16(W2[k][n]) ----
        const int t = (b - G_GATHER - G_REST - G_WT1) * 256 + (int)threadIdx.x;
        const int n = t / (HIDDEN / 4);
        const int k = (t % (HIDDEN / 4)) * 4;
        const size_t o = (size_t)n * HIDDEN + k;
        __half2 p0(__float2half_rn(W2[(size_t)(k + 0) * NODE_F + n]),
                   __float2half_rn(W2[(size_t)(k + 1) * NODE_F + n]));
        __half2 p1(__float2half_rn(W2[(size_t)(k + 2) * NODE_F + n]),
                   __float2half_rn(W2[(size_t)(k + 3) * NODE_F + n]));
        reinterpret_cast<__half2*>(g_Wt2 + o)[0] = p0;
        reinterpret_cast<__half2*>(g_Wt2 + o)[1] = p1;
    } else {
        // ---- ub1[g][n] = b1[n] + sum_k u[g,k] * W1[544+k][n]  (full f32) ----
        const int t = (b - G_GATHER - G_REST - G_WT1 - G_WT2) * 256 + (int)threadIdx.x;
        const int g = t >> 10;
        const int n = t & 1023;
        if (g >= 8) return;
        float s = b1[n];
        #pragma unroll 8
        for (int k = 0; k < GLOB_F; k++)
            s = fmaf(u[g * GLOB_F + k], W1[(size_t)(KH + k) * HIDDEN + n], s);
        g_ub1[g * HIDDEN + n] = s;
    }
}

// ============== asymmetric-split fp16 GEMM on mma.sync =====================
// C[128,128]/CTA, 8 warps 2(M)x4(N), warp tile 64x32, KC=32, S=3, 2 CTAs/SM.
// A split exactly (Ah+Al), B rounded to fp16: acc = Ah*Bh + Al*Bh = A*Bh.
// 2 MMAs per (am,an) K=16 region; 3 smem tiles/stage (Ah, Al, Bh) = 24KB.
// MODE 0: out = relu(acc + ub1[batch[row]][col]) -> fp16 hi/lo
// MODE 1: out = acc + bias[col] + resid -> f32
template<int K_TOTAL, int N_TOTAL, int MODE>
__global__ void __launch_bounds__(256, 2) hmma_gemm_kernel(
    const __half* __restrict__ Ah, const __half* __restrict__ Al,
    const __half* __restrict__ Bh,
    const float* __restrict__ bias, const float* __restrict__ resid,
    const int* __restrict__ batchp,
    __half* __restrict__ outh, __half* __restrict__ outl,
    float* __restrict__ outf, int M)
{
    constexpr int KC = 32;
    constexpr int S  = 3;
    constexpr int TILE_B = 128 * 64;      // 8192
    constexpr int STAGE_B = 3 * TILE_B;   // Ah, Al, Bh
    constexpr int NCH = K_TOTAL / KC;

    extern __shared__ char smem[];
    const uint32_t smem_u = smem_to_u32(smem);

    const int tid = threadIdx.x;
    const int lid = tid & 31;
    const int wid = tid >> 5;
    const int warp_m = wid & 1;
    const int warp_n = wid >> 1;
    const int blockN = blockIdx.x * 128;
    const int blockM = blockIdx.y * 128;

    float acc[64];
    #pragma unroll
    for (int i = 0; i < 64; i++) acc[i] = 0.0f;

    const int ldrow0 = tid >> 2;
    const int ldseg  = tid & 3;

    auto load_chunk = [&](int c) {
        if (c >= NCH) return;
        const int kb = c * KC;
        const uint32_t sb = smem_u + (uint32_t)(c % S) * STAGE_B;
        #pragma unroll
        for (int i = 0; i < 2; i++) {
            const int row = ldrow0 + 64 * i;
            const uint32_t doff = sw_off(row, ldseg);
            const int gr = blockM + row;
            const bool v = gr < M;
            const size_t goA = (size_t)(v ? gr : 0) * K_TOTAL + kb + ldseg * 8;
            cp16(sb + 0 * TILE_B + doff, Ah + goA, v);
            cp16(sb + 1 * TILE_B + doff, Al + goA, v);
            const size_t goB = (size_t)(blockN + row) * K_TOTAL + kb + ldseg * 8;
            cp16(sb + 2 * TILE_B + doff, Bh + goB, true);
        }
    };

    #pragma unroll
    for (int c = 0; c < S - 1; c++) {
        load_chunk(c);
        CP_COMMIT();
    }

    const int lr = lid & 15;
    const int lk = (lid >> 4) * 8;

    for (int c = 0; c < NCH; c++) {
        load_chunk(c + S - 1);
        CP_COMMIT();
        CP_WAIT(S - 1);
        __syncthreads();

        const uint32_t sb = smem_u + (uint32_t)(c % S) * STAGE_B;
        const uint32_t aH = sb, aL = sb + TILE_B, bH = sb + 2 * TILE_B;

        #pragma unroll
        for (int kk = 0; kk < KC; kk += 16) {
            const int kchunk = (kk + lk) >> 3;
            uint32_t bh[8];
            #pragma unroll
            for (int bn = 0; bn < 2; bn++) {
                const uint32_t off = sw_off(warp_n * 32 + bn * 16 + lr, kchunk);
                ldsm4(&bh[bn * 4], bH + off);
            }
            #pragma unroll
            for (int am = 0; am < 4; am++) {
                uint32_t ah[4], al[4];
                const uint32_t off = sw_off(warp_m * 64 + am * 16 + lr, kchunk);
                ldsm4(ah, aH + off);
                ldsm4(al, aL + off);
                #pragma unroll
                for (int an = 0; an < 4; an++) {
                    const int bn = an >> 1, sel = an & 1;
                    float* d = &acc[(am * 4 + an) * 4];
                    const uint32_t h0 = bh[bn * 4 + sel], h1 = bh[bn * 4 + sel + 2];
                    mma16816(d, ah, h0, h1);
                    mma16816(d, al, h0, h1);
                }
            }
        }
        __syncthreads();
    }

    const int g = lid >> 2;
    const int t = lid & 3;
    #pragma unroll
    for (int am = 0; am < 4; am++) {
        #pragma unroll
        for (int an = 0; an < 4; an++) {
            const float* d = &acc[(am * 4 + an) * 4];
            const int col = blockN + warp_n * 32 + an * 8 + 2 * t;
            #pragma unroll
            for (int half = 0; half < 2; half++) {
                const int row = blockM + warp_m * 64 + am * 16 + g + half * 8;
                if (row >= M) continue;
                float bia0, bia1;
                if (MODE == 0) {
                    const int gg = batchp[row];
                    bia0 = bias[gg * N_TOTAL + col];
                    bia1 = bias[gg * N_TOTAL + col + 1];
                } else {
                    bia0 = bias[col];
                    bia1 = bias[col + 1];
                }
                float v0 = d[half * 2 + 0] + bia0;
                float v1 = d[half * 2 + 1] + bia1;
                const size_t o = (size_t)row * N_TOTAL + col;
                if (MODE == 0) {
                    v0 = fmaxf(v0, 0.0f);
                    v1 = fmaxf(v1, 0.0f);
                    __half h0, l0, h1, l1;
                    split_f16(v0, h0, l0);
                    split_f16(v1, h1, l1);
                    __half2 ph(h0, h1), pl(l0, l1);
                    *reinterpret_cast<uint32_t*>(outh + o) = *reinterpret_cast<uint32_t*>(&ph);
                    *reinterpret_cast<uint32_t*>(outl + o) = *reinterpret_cast<uint32_t*>(&pl);
                } else {
                    float2 r;
                    r.x = v0 + resid[o];
                    r.y = v1 + resid[o + 1];
                    *reinterpret_cast<float2*>(outf + o) = r;
                }
            }
        }
    }
}

// ---------------- launch ----------------
extern "C" void kernel_launch(void* const* d_in, const int* in_sizes, int n_in,
                              void* d_out, int out_size) {
    const float* x         = (const float*)d_in[0];
    const float* edge_attr = (const float*)d_in[1];
    const float* u         = (const float*)d_in[2];
    const float* W1        = (const float*)d_in[3];
    const float* b1        = (const float*)d_in[4];
    const float* W2        = (const float*)d_in[5];
    const float* b2        = (const float*)d_in[6];
    const int*   edge_index= (const int*)d_in[7];
    const int*   batch     = (const int*)d_in[8];
    float* out = (float*)d_out;

    const int* col = edge_index + N_EDGES;

    __half *pHh, *pHl, *pMh, *pMl, *pW1, *pW2;
    float* pUb1;
    cudaGetSymbolAddress((void**)&pHh, g_Hh);
    cudaGetSymbolAddress((void**)&pHl, g_Hl);
    cudaGetSymbolAddress((void**)&pMh, g_midh);
    cudaGetSymbolAddress((void**)&pMl, g_midl);
    cudaGetSymbolAddress((void**)&pW1, g_Wt1);
    cudaGetSymbolAddress((void**)&pW2, g_Wt2);
    cudaGetSymbolAddress((void**)&pUb1, g_ub1);

    const int SMEM_BYTES = 3 * 3 * 128 * 64;   // 73728
    cudaFuncSetAttribute(hmma_gemm_kernel<KH, HIDDEN, 0>,
                         cudaFuncAttributeMaxDynamicSharedMemorySize, SMEM_BYTES);
    cudaFuncSetAttribute(hmma_gemm_kernel<HIDDEN, NODE_F, 1>,
                         cudaFuncAttributeMaxDynamicSharedMemorySize, SMEM_BYTES);

    // 1-3) CSR
    count_kernel<<<(N_EDGES + 255) / 256, 256>>>(col);
    scan_kernel<<<1, 1024>>>();
    fill_kernel<<<(N_EDGES + 255) / 256, 256>>>(col);
    // 4) merged prep
    prep_kernel<<<G_GATHER + G_REST + G_WT1 + G_WT2 + G_UB1, 256>>>(
        edge_attr, x, u, W1, b1, W2);
    // 5) GEMM1: mid = relu(H @ W1[0:544] + ub1[batch])  [50000,1024]
    {
        dim3 grid(HIDDEN / 128, (N_NODES + 127) / 128);
        hmma_gemm_kernel<KH, HIDDEN, 0><<<grid, 256, SMEM_BYTES>>>(
            pHh, pHl, pW1, pUb1, nullptr, batch, pMh, pMl, nullptr, N_NODES);
    }
    // 6) GEMM2: out = mid @ W2 + b2 + x  [50000,256]
    {
        dim3 grid(NODE_F / 128, (N_NODES + 127) / 128);
        hmma_gemm_kernel<HIDDEN, NODE_F, 1><<<grid, 256, SMEM_BYTES>>>(
            pMh, pMl, pW2, b2, x, nullptr, nullptr, nullptr, out, N_NODES);
    }
}

// round 14
// speedup vs baseline: 2.4486x; 1.4398x over previous
#include <cuda_runtime.h>
#include <cuda_fp16.h>
#include <stdint.h>

#define N_NODES 50000
#define N_EDGES 800000
#define EDGE_F  96
#define NODE_F  256
#define GLOB_F  64
#define HIDDEN  1024
#define MLP_IN  608
#define KH      544   // GEMM1 K: x(256) + sum/max/mean(288); u folded into bias table

// ---------------- scratch (device globals: allocation-free) ----------------
__device__ int g_deg[N_NODES];        // zero at load; fill_kernel re-zeros each run
__device__ int g_off[N_NODES + 1];
__device__ int g_cur[N_NODES];
__device__ int g_bin[N_EDGES];
__device__ float g_ub1[8 * HIDDEN];   // per-graph bias: b1 + u[g] @ W1[544:608]
// fp16 operands (both sides rounded; 10-bit mantissa == tf32 accuracy class)
__device__ alignas(16) __half g_H[(size_t)N_NODES * KH];
__device__ alignas(16) __half g_mid[(size_t)N_NODES * HIDDEN];
__device__ alignas(16) __half g_Wt1[(size_t)HIDDEN * KH];      // [n][k]
__device__ alignas(16) __half g_Wt2[(size_t)NODE_F * HIDDEN];  // [n][k]

// ======================= helpers ===========================================
__device__ __forceinline__ uint32_t smem_to_u32(const void* p) {
    uint32_t a;
    asm("{ .reg .u64 t; cvta.to.shared.u64 t, %1; cvt.u32.u64 %0, t; }"
        : "=r"(a) : "l"(p));
    return a;
}

__device__ __forceinline__ void cp16(uint32_t dst, const void* src, bool valid) {
    asm volatile("cp.async.cg.shared.global [%0], [%1], 16, %2;"
                 :: "r"(dst), "l"(src), "r"(valid ? 16 : 0));
}
#define CP_COMMIT() asm volatile("cp.async.commit_group;" ::: "memory")
#define CP_WAIT(n)  asm volatile("cp.async.wait_group %0;" :: "n"(n) : "memory")

__device__ __forceinline__ void ldsm4(uint32_t* r, uint32_t addr) {
    asm volatile("ldmatrix.sync.aligned.m8n8.x4.shared.b16 {%0,%1,%2,%3}, [%4];"
                 : "=r"(r[0]), "=r"(r[1]), "=r"(r[2]), "=r"(r[3]) : "r"(addr));
}

// fp16 mma with f32 accumulate: D[16x8] += A[16x16] * B[16x8]
__device__ __forceinline__ void mma16816(float* d, const uint32_t* a,
                                         uint32_t b0, uint32_t b1) {
    asm volatile(
        "mma.sync.aligned.m16n8k16.row.col.f32.f16.f16.f32 "
        "{%0,%1,%2,%3}, {%4,%5,%6,%7}, {%8,%9}, {%0,%1,%2,%3};"
        : "+f"(d[0]), "+f"(d[1]), "+f"(d[2]), "+f"(d[3])
        : "r"(a[0]), "r"(a[1]), "r"(a[2]), "r"(a[3]), "r"(b0), "r"(b1));
}

// 64B-row smem tile with XOR swizzle (conflict-free for 8-lane ldmatrix phases)
__device__ __forceinline__ uint32_t sw_off(int row, int chunk) {
    return (uint32_t)row * 64u + (uint32_t)((chunk ^ ((row >> 1) & 3)) << 4);
}

// ===================== CSR build ===========================================
__global__ void count_kernel(const int* __restrict__ col) {
    int e = blockIdx.x * blockDim.x + threadIdx.x;
    if (e < N_EDGES) atomicAdd(&g_deg[col[e]], 1);
}

__global__ void scan_kernel() {
    __shared__ int warp_sums[32];
    __shared__ int carry_s;
    const int tid = threadIdx.x;
    const int lane = tid & 31, wid = tid >> 5;
    if (tid == 0) carry_s = 0;
    __syncthreads();
    for (int base = 0; base < N_NODES; base += 1024) {
        int i = base + tid;
        int v = (i < N_NODES) ? g_deg[i] : 0;
        int x = v;
        #pragma unroll
        for (int o = 1; o < 32; o <<= 1) {
            int y = __shfl_up_sync(0xFFFFFFFFu, x, o);
            if (lane >= o) x += y;
        }
        if (lane == 31) warp_sums[wid] = x;
        __syncthreads();
        if (wid == 0) {
            int w = warp_sums[lane];
            #pragma unroll
            for (int o = 1; o < 32; o <<= 1) {
                int y = __shfl_up_sync(0xFFFFFFFFu, w, o);
                if (lane >= o) w += y;
            }
            warp_sums[lane] = w;
        }
        __syncthreads();
        int excl = x - v + (wid > 0 ? warp_sums[wid - 1] : 0) + carry_s;
        if (i < N_NODES) {
            g_off[i] = excl;
            g_cur[i] = excl;
        }
        __syncthreads();
        if (tid == 0) carry_s += warp_sums[31];
        __syncthreads();
    }
    if (tid == 0) g_off[N_NODES] = N_EDGES;
}

__global__ void fill_kernel(const int* __restrict__ col) {
    int e = blockIdx.x * blockDim.x + threadIdx.x;
    if (e < N_EDGES) {
        int pos = atomicAdd(&g_cur[col[e]], 1);
        g_bin[pos] = e;
    }
    if (e < N_NODES) g_deg[e] = 0;
}

// ============ merged prep: gather | rest(x) | wt1 | wt2 | ub1 ==============
#define G_GATHER 6250                          // 50000 warps, 8/block
#define G_REST   12500                         // 50000*256/4 /256
#define G_WT1    (HIDDEN * (KH / 4) / 256)     // 544
#define G_WT2    (NODE_F * (HIDDEN / 4) / 256) // 256
#define G_UB1    32

__global__ void prep_kernel(const float* __restrict__ edge_attr,
                            const float* __restrict__ x,
                            const float* __restrict__ u,
                            const float* __restrict__ W1,
                            const float* __restrict__ b1,
                            const float* __restrict__ W2) {
    const int b = blockIdx.x;
    if (b < G_GATHER) {
        // ---- gather: warp per node -> H cols [256,544), fp16 ----
        const int warp_g = (b * 256 + (int)threadIdx.x) >> 5;
        if (warp_g >= N_NODES) return;
        const int lane = threadIdx.x & 31;
        const int beg = g_off[warp_g];
        const int end = g_off[warp_g + 1];

        float s0 = 0.f, s1 = 0.f, s2 = 0.f;
        float m0 = -__int_as_float(0x7F800000), m1 = m0, m2 = m0;

        for (int i = beg; i < end; i++) {
            const int e = g_bin[i];
            const float* row = edge_attr + (size_t)e * EDGE_F;
            float v0 = row[lane];
            float v1 = row[lane + 32];
            float v2 = row[lane + 64];
            s0 += v0; s1 += v1; s2 += v2;
            m0 = fmaxf(m0, v0); m1 = fmaxf(m1, v1); m2 = fmaxf(m2, v2);
        }
        const int cnt = end - beg;
        if (cnt == 0) { m0 = 0.f; m1 = 0.f; m2 = 0.f; }
        const float inv = 1.0f / (float)max(cnt, 1);

        __half* H = g_H + (size_t)warp_g * KH;
        H[256 + lane] = __float2half_rn(s0);
        H[288 + lane] = __float2half_rn(s1);
        H[320 + lane] = __float2half_rn(s2);
        H[352 + lane] = __float2half_rn(m0);
        H[384 + lane] = __float2half_rn(m1);
        H[416 + lane] = __float2half_rn(m2);
        H[448 + lane] = __float2half_rn(s0 * inv);
        H[480 + lane] = __float2half_rn(s1 * inv);
        H[512 + lane] = __float2half_rn(s2 * inv);
    } else if (b < G_GATHER + G_REST) {
        // ---- rest: H cols [0,256) = fp16(x), x4 ----
        const int t = (b - G_GATHER) * 256 + (int)threadIdx.x;
        const int n = t >> 6;
        const int c = (t & 63) * 4;
        if (n >= N_NODES) return;
        const float4 v = *reinterpret_cast<const float4*>(x + (size_t)n * NODE_F + c);
        const size_t o = (size_t)n * KH + c;
        __half2 p0(__float2half_rn(v.x), __float2half_rn(v.y));
        __half2 p1(__float2half_rn(v.z), __float2half_rn(v.w));
        reinterpret_cast<__half2*>(g_H + o)[0] = p0;
        reinterpret_cast<__half2*>(g_H + o)[1] = p1;
    } else if (b < G_GATHER + G_REST + G_WT1) {
        // ---- wt1: Wt1[n][k] = fp16(W1[k][n]), k in [0,544) ----
        const int t = (b - G_GATHER - G_REST) * 256 + (int)threadIdx.x;
        const int n = t / (KH / 4);
        const int k = (t % (KH / 4)) * 4;
        const size_t o = (size_t)n * KH + k;
        __half2 p0(__float2half_rn(W1[(size_t)(k + 0) * HIDDEN + n]),
                   __float2half_rn(W1[(size_t)(k + 1) * HIDDEN + n]));
        __half2 p1(__float2half_rn(W1[(size_t)(k + 2) * HIDDEN + n]),
                   __float2half_rn(W1[(size_t)(k + 3) * HIDDEN + n]));
        reinterpret_cast<__half2*>(g_Wt1 + o)[0] = p0;
        reinterpret_cast<__half2*>(g_Wt1 + o)[1] = p1;
    } else if (b < G_GATHER + G_REST + G_WT1 + G_WT2) {
        // ---- wt2: Wt2[n][k] = fp16(W2[k][n]) ----
        const int t = (b - G_GATHER - G_REST - G_WT1) * 256 + (int)threadIdx.x;
        const int n = t / (HIDDEN / 4);
        const int k = (t % (HIDDEN / 4)) * 4;
        const size_t o = (size_t)n * HIDDEN + k;
        __half2 p0(__float2half_rn(W2[(size_t)(k + 0) * NODE_F + n]),
                   __float2half_rn(W2[(size_t)(k + 1) * NODE_F + n]));
        __half2 p1(__float2half_rn(W2[(size_t)(k + 2) * NODE_F + n]),
                   __float2half_rn(W2[(size_t)(k + 3) * NODE_F + n]));
        reinterpret_cast<__half2*>(g_Wt2 + o)[0] = p0;
        reinterpret_cast<__half2*>(g_Wt2 + o)[1] = p1;
    } else {
        // ---- ub1[g][n] = b1[n] + sum_k u[g,k] * W1[544+k][n]  (full f32) ----
        const int t = (b - G_GATHER - G_REST - G_WT1 - G_WT2) * 256 + (int)threadIdx.x;
        const int g = t >> 10;
        const int n = t & 1023;
        if (g >= 8) return;
        float s = b1[n];
        #pragma unroll 8
        for (int k = 0; k < GLOB_F; k++)
            s = fmaf(u[g * GLOB_F + k], W1[(size_t)(KH + k) * HIDDEN + n], s);
        g_ub1[g * HIDDEN + n] = s;
    }
}

// ================== plain fp16 GEMM on mma.sync ============================
// C[128,128]/CTA, 8 warps 2(M)x4(N), warp tile 64x32, KC=32, S=3, 2 CTAs/SM.
// Both operands fp16 (10-bit mantissa, RN) — tf32-class accuracy, 1 MMA per
// K=16 region. 2 smem tiles/stage (A, B) = 16KB.
// MODE 0: out = relu(acc + ub1[batch[row]][col]) -> fp16
// MODE 1: out = acc + bias[col] + resid -> f32
template<int K_TOTAL, int N_TOTAL, int MODE>
__global__ void __launch_bounds__(256, 2) hmma_gemm_kernel(
    const __half* __restrict__ A, const __half* __restrict__ B,
    const float* __restrict__ bias, const float* __restrict__ resid,
    const int* __restrict__ batchp,
    __half* __restrict__ outh, float* __restrict__ outf, int M)
{
    constexpr int KC = 32;
    constexpr int S  = 3;
    constexpr int TILE_B = 128 * 64;      // 8192
    constexpr int STAGE_B = 2 * TILE_B;   // A, B
    constexpr int NCH = K_TOTAL / KC;

    extern __shared__ char smem[];
    const uint32_t smem_u = smem_to_u32(smem);

    const int tid = threadIdx.x;
    const int lid = tid & 31;
    const int wid = tid >> 5;
    const int warp_m = wid & 1;
    const int warp_n = wid >> 1;
    const int blockN = blockIdx.x * 128;
    const int blockM = blockIdx.y * 128;

    float acc[64];
    #pragma unroll
    for (int i = 0; i < 64; i++) acc[i] = 0.0f;

    const int ldrow0 = tid >> 2;
    const int ldseg  = tid & 3;

    auto load_chunk = [&](int c) {
        if (c >= NCH) return;
        const int kb = c * KC;
        const uint32_t sb = smem_u + (uint32_t)(c % S) * STAGE_B;
        #pragma unroll
        for (int i = 0; i < 2; i++) {
            const int row = ldrow0 + 64 * i;
            const uint32_t doff = sw_off(row, ldseg);
            const int gr = blockM + row;
            const bool v = gr < M;
            const size_t goA = (size_t)(v ? gr : 0) * K_TOTAL + kb + ldseg * 8;
            cp16(sb + doff, A + goA, v);
            const size_t goB = (size_t)(blockN + row) * K_TOTAL + kb + ldseg * 8;
            cp16(sb + TILE_B + doff, B + goB, true);
        }
    };

    #pragma unroll
    for (int c = 0; c < S - 1; c++) {
        load_chunk(c);
        CP_COMMIT();
    }

    const int lr = lid & 15;
    const int lk = (lid >> 4) * 8;

    for (int c = 0; c < NCH; c++) {
        load_chunk(c + S - 1);
        CP_COMMIT();
        CP_WAIT(S - 1);
        __syncthreads();

        const uint32_t sb = smem_u + (uint32_t)(c % S) * STAGE_B;
        const uint32_t aT = sb, bT = sb + TILE_B;

        #pragma unroll
        for (int kk = 0; kk < KC; kk += 16) {
            const int kchunk = (kk + lk) >> 3;
            uint32_t bh[8];
            #pragma unroll
            for (int bn = 0; bn < 2; bn++) {
                const uint32_t off = sw_off(warp_n * 32 + bn * 16 + lr, kchunk);
                ldsm4(&bh[bn * 4], bT + off);
            }
            #pragma unroll
            for (int am = 0; am < 4; am++) {
                uint32_t ah[4];
                const uint32_t off = sw_off(warp_m * 64 + am * 16 + lr, kchunk);
                ldsm4(ah, aT + off);
                #pragma unroll
                for (int an = 0; an < 4; an++) {
                    const int bn = an >> 1, sel = an & 1;
                    float* d = &acc[(am * 4 + an) * 4];
                    mma16816(d, ah, bh[bn * 4 + sel], bh[bn * 4 + sel + 2]);
                }
            }
        }
        __syncthreads();
    }

    const int g = lid >> 2;
    const int t = lid & 3;
    #pragma unroll
    for (int am = 0; am < 4; am++) {
        #pragma unroll
        for (int an = 0; an < 4; an++) {
            const float* d = &acc[(am * 4 + an) * 4];
            const int col = blockN + warp_n * 32 + an * 8 + 2 * t;
            #pragma unroll
            for (int half = 0; half < 2; half++) {
                const int row = blockM + warp_m * 64 + am * 16 + g + half * 8;
                if (row >= M) continue;
                float bia0, bia1;
                if (MODE == 0) {
                    const int gg = batchp[row];
                    bia0 = bias[gg * N_TOTAL + col];
                    bia1 = bias[gg * N_TOTAL + col + 1];
                } else {
                    bia0 = bias[col];
                    bia1 = bias[col + 1];
                }
                float v0 = d[half * 2 + 0] + bia0;
                float v1 = d[half * 2 + 1] + bia1;
                const size_t o = (size_t)row * N_TOTAL + col;
                if (MODE == 0) {
                    __half2 p(__float2half_rn(fmaxf(v0, 0.0f)),
                              __float2half_rn(fmaxf(v1, 0.0f)));
                    *reinterpret_cast<uint32_t*>(outh + o) = *reinterpret_cast<uint32_t*>(&p);
                } else {
                    float2 r;
                    r.x = v0 + resid[o];
                    r.y = v1 + resid[o + 1];
                    *reinterpret_cast<float2*>(outf + o) = r;
                }
            }
        }
    }
}

// ---------------- launch ----------------
extern "C" void kernel_launch(void* const* d_in, const int* in_sizes, int n_in,
                              void* d_out, int out_size) {
    const float* x         = (const float*)d_in[0];
    const float* edge_attr = (const float*)d_in[1];
    const float* u         = (const float*)d_in[2];
    const float* W1        = (const float*)d_in[3];
    const float* b1        = (const float*)d_in[4];
    const float* W2        = (const float*)d_in[5];
    const float* b2        = (const float*)d_in[6];
    const int*   edge_index= (const int*)d_in[7];
    const int*   batch     = (const int*)d_in[8];
    float* out = (float*)d_out;

    const int* col = edge_index + N_EDGES;

    __half *pH, *pMid, *pW1, *pW2;
    float* pUb1;
    cudaGetSymbolAddress((void**)&pH,  g_H);
    cudaGetSymbolAddress((void**)&pMid, g_mid);
    cudaGetSymbolAddress((void**)&pW1, g_Wt1);
    cudaGetSymbolAddress((void**)&pW2, g_Wt2);
    cudaGetSymbolAddress((void**)&pUb1, g_ub1);

    const int SMEM_BYTES = 3 * 2 * 128 * 64;   // 49152
    cudaFuncSetAttribute(hmma_gemm_kernel<KH, HIDDEN, 0>,
                         cudaFuncAttributeMaxDynamicSharedMemorySize, SMEM_BYTES);
    cudaFuncSetAttribute(hmma_gemm_kernel<HIDDEN, NODE_F, 1>,
                         cudaFuncAttributeMaxDynamicSharedMemorySize, SMEM_BYTES);

    // 1-3) CSR
    count_kernel<<<(N_EDGES + 255) / 256, 256>>>(col);
    scan_kernel<<<1, 1024>>>();
    fill_kernel<<<(N_EDGES + 255) / 256, 256>>>(col);
    // 4) merged prep
    prep_kernel<<<G_GATHER + G_REST + G_WT1 + G_WT2 + G_UB1, 256>>>(
        edge_attr, x, u, W1, b1, W2);
    // 5) GEMM1: mid = relu(H @ W1[0:544] + ub1[batch])  [50000,1024]
    {
        dim3 grid(HIDDEN / 128, (N_NODES + 127) / 128);
        hmma_gemm_kernel<KH, HIDDEN, 0><<<grid, 256, SMEM_BYTES>>>(
            pH, pW1, pUb1, nullptr, batch, pMid, nullptr, N_NODES);
    }
    // 6) GEMM2: out = mid @ W2 + b2 + x  [50000,256]
    {
        dim3 grid(NODE_F / 128, (N_NODES + 127) / 128);
        hmma_gemm_kernel<HIDDEN, NODE_F, 1><<<grid, 256, SMEM_BYTES>>>(
            pMid, pW2, b2, x, nullptr, nullptr, out, N_NODES);
    }
}

// round 15
// speedup vs baseline: 2.6373x; 1.0770x over previous
#include <cuda_runtime.h>
#include <cuda_fp16.h>
#include <stdint.h>

#define N_NODES 50000
#define N_EDGES 800000
#define EDGE_F  96
#define NODE_F  256
#define GLOB_F  64
#define HIDDEN  1024
#define MLP_IN  608
#define KH      544   // GEMM1 K: x(256) + sum/max/mean(288); u folded into bias table

// ---------------- scratch (device globals: allocation-free) ----------------
__device__ alignas(16) int g_deg[N_NODES];   // zero at load; fill_kernel re-zeros
__device__ alignas(16) int g_off[N_NODES + 4];
__device__ alignas(16) int g_cur[N_NODES];
__device__ int g_bin[N_EDGES];
__device__ float g_ub1[8 * HIDDEN];   // per-graph bias: b1 + u[g] @ W1[544:608]
// fp16 operands (both sides rounded; 10-bit mantissa == tf32 accuracy class)
__device__ alignas(16) __half g_H[(size_t)N_NODES * KH];
__device__ alignas(16) __half g_mid[(size_t)N_NODES * HIDDEN];
__device__ alignas(16) __half g_Wt1[(size_t)HIDDEN * KH];      // [n][k]
__device__ alignas(16) __half g_Wt2[(size_t)NODE_F * HIDDEN];  // [n][k]

// ======================= helpers ===========================================
__device__ __forceinline__ uint32_t smem_to_u32(const void* p) {
    uint32_t a;
    asm("{ .reg .u64 t; cvta.to.shared.u64 t, %1; cvt.u32.u64 %0, t; }"
        : "=r"(a) : "l"(p));
    return a;
}

__device__ __forceinline__ void cp16(uint32_t dst, const void* src, bool valid) {
    asm volatile("cp.async.cg.shared.global [%0], [%1], 16, %2;"
                 :: "r"(dst), "l"(src), "r"(valid ? 16 : 0));
}
#define CP_COMMIT() asm volatile("cp.async.commit_group;" ::: "memory")
#define CP_WAIT(n)  asm volatile("cp.async.wait_group %0;" :: "n"(n) : "memory")

__device__ __forceinline__ void ldsm4(uint32_t* r, uint32_t addr) {
    asm volatile("ldmatrix.sync.aligned.m8n8.x4.shared.b16 {%0,%1,%2,%3}, [%4];"
                 : "=r"(r[0]), "=r"(r[1]), "=r"(r[2]), "=r"(r[3]) : "r"(addr));
}

// fp16 mma with f32 accumulate: D[16x8] += A[16x16] * B[16x8]
__device__ __forceinline__ void mma16816(float* d, const uint32_t* a,
                                         uint32_t b0, uint32_t b1) {
    asm volatile(
        "mma.sync.aligned.m16n8k16.row.col.f32.f16.f16.f32 "
        "{%0,%1,%2,%3}, {%4,%5,%6,%7}, {%8,%9}, {%0,%1,%2,%3};"
        : "+f"(d[0]), "+f"(d[1]), "+f"(d[2]), "+f"(d[3])
        : "r"(a[0]), "r"(a[1]), "r"(a[2]), "r"(a[3]), "r"(b0), "r"(b1));
}

// 64B-row smem tile with XOR swizzle (conflict-free for 8-lane ldmatrix phases)
__device__ __forceinline__ uint32_t sw_off(int row, int chunk) {
    return (uint32_t)row * 64u + (uint32_t)((chunk ^ ((row >> 1) & 3)) << 4);
}

// =============== kernel A: count + CSR-independent prep ====================
// block-range dispatch; count runs concurrently with x/W/ub1 conversion.
#define A_COUNT 3125                           // 800000/256
#define A_REST  12500                          // 50000*256/4 /256
#define A_WT1   (HIDDEN * (KH / 4) / 256)      // 544
#define A_WT2   (NODE_F * (HIDDEN / 4) / 256)  // 256
#define A_UB1   32

__global__ void count_prep_kernel(const int* __restrict__ col,
                                  const float* __restrict__ x,
                                  const float* __restrict__ u,
                                  const float* __restrict__ W1,
                                  const float* __restrict__ b1,
                                  const float* __restrict__ W2) {
    const int b = blockIdx.x;
    if (b < A_COUNT) {
        int e = b * 256 + (int)threadIdx.x;
        if (e < N_EDGES) atomicAdd(&g_deg[col[e]], 1);
    } else if (b < A_COUNT + A_REST) {
        // ---- H cols [0,256) = fp16(x), x4 ----
        const int t = (b - A_COUNT) * 256 + (int)threadIdx.x;
        const int n = t >> 6;
        const int c = (t & 63) * 4;
        if (n >= N_NODES) return;
        const float4 v = *reinterpret_cast<const float4*>(x + (size_t)n * NODE_F + c);
        const size_t o = (size_t)n * KH + c;
        __half2 p0(__float2half_rn(v.x), __float2half_rn(v.y));
        __half2 p1(__float2half_rn(v.z), __float2half_rn(v.w));
        reinterpret_cast<__half2*>(g_H + o)[0] = p0;
        reinterpret_cast<__half2*>(g_H + o)[1] = p1;
    } else if (b < A_COUNT + A_REST + A_WT1) {
        // ---- Wt1[n][k] = fp16(W1[k][n]), k in [0,544) ----
        const int t = (b - A_COUNT - A_REST) * 256 + (int)threadIdx.x;
        const int n = t / (KH / 4);
        const int k = (t % (KH / 4)) * 4;
        const size_t o = (size_t)n * KH + k;
        __half2 p0(__float2half_rn(W1[(size_t)(k + 0) * HIDDEN + n]),
                   __float2half_rn(W1[(size_t)(k + 1) * HIDDEN + n]));
        __half2 p1(__float2half_rn(W1[(size_t)(k + 2) * HIDDEN + n]),
                   __float2half_rn(W1[(size_t)(k + 3) * HIDDEN + n]));
        reinterpret_cast<__half2*>(g_Wt1 + o)[0] = p0;
        reinterpret_cast<__half2*>(g_Wt1 + o)[1] = p1;
    } else if (b < A_COUNT + A_REST + A_WT1 + A_WT2) {
        // ---- Wt2[n][k] = fp16(W2[k][n]) ----
        const int t = (b - A_COUNT - A_REST - A_WT1) * 256 + (int)threadIdx.x;
        const int n = t / (HIDDEN / 4);
        const int k = (t % (HIDDEN / 4)) * 4;
        const size_t o = (size_t)n * HIDDEN + k;
        __half2 p0(__float2half_rn(W2[(size_t)(k + 0) * NODE_F + n]),
                   __float2half_rn(W2[(size_t)(k + 1) * NODE_F + n]));
        __half2 p1(__float2half_rn(W2[(size_t)(k + 2) * NODE_F + n]),
                   __float2half_rn(W2[(size_t)(k + 3) * NODE_F + n]));
        reinterpret_cast<__half2*>(g_Wt2 + o)[0] = p0;
        reinterpret_cast<__half2*>(g_Wt2 + o)[1] = p1;
    } else {
        // ---- ub1[g][n] = b1[n] + sum_k u[g,k] * W1[544+k][n]  (full f32) ----
        const int t = (b - A_COUNT - A_REST - A_WT1 - A_WT2) * 256 + (int)threadIdx.x;
        const int g = t >> 10;
        const int n = t & 1023;
        if (g >= 8) return;
        float s = b1[n];
        #pragma unroll 8
        for (int k = 0; k < GLOB_F; k++)
            s = fmaf(u[g * GLOB_F + k], W1[(size_t)(KH + k) * HIDDEN + n], s);
        g_ub1[g * HIDDEN + n] = s;
    }
}

// ===================== scan: 4 elems/thread, 13 iterations =================
__global__ void scan_kernel() {
    __shared__ int warp_sums[32];
    __shared__ int carry_s;
    const int tid = threadIdx.x;
    const int lane = tid & 31, wid = tid >> 5;
    if (tid == 0) carry_s = 0;
    __syncthreads();
    for (int base = 0; base < N_NODES; base += 4096) {
        const int i = base + tid * 4;
        int4 v = make_int4(0, 0, 0, 0);
        if (i < N_NODES)  // N_NODES % 4 == 0 -> full vector in bounds
            v = *reinterpret_cast<const int4*>(g_deg + i);
        const int s = v.x + v.y + v.z + v.w;
        int xval = s;
        #pragma unroll
        for (int o = 1; o < 32; o <<= 1) {
            int y = __shfl_up_sync(0xFFFFFFFFu, xval, o);
            if (lane >= o) xval += y;
        }
        if (lane == 31) warp_sums[wid] = xval;
        __syncthreads();
        if (wid == 0) {
            int w = warp_sums[lane];
            #pragma unroll
            for (int o = 1; o < 32; o <<= 1) {
                int y = __shfl_up_sync(0xFFFFFFFFu, w, o);
                if (lane >= o) w += y;
            }
            warp_sums[lane] = w;
        }
        __syncthreads();
        const int excl = xval - s + (wid > 0 ? warp_sums[wid - 1] : 0) + carry_s;
        if (i < N_NODES) {
            int4 e;
            e.x = excl;
            e.y = e.x + v.x;
            e.z = e.y + v.y;
            e.w = e.z + v.z;
            *reinterpret_cast<int4*>(g_off + i) = e;
            *reinterpret_cast<int4*>(g_cur + i) = e;
        }
        __syncthreads();
        if (tid == 0) carry_s += warp_sums[31];
        __syncthreads();
    }
    if (tid == 0) g_off[N_NODES] = N_EDGES;
}

// fill bins; also re-zero g_deg so the next replay starts clean (deterministic)
__global__ void fill_kernel(const int* __restrict__ col) {
    int e = blockIdx.x * blockDim.x + threadIdx.x;
    if (e < N_EDGES) {
        int pos = atomicAdd(&g_cur[col[e]], 1);
        g_bin[pos] = e;
    }
    if (e < N_NODES) g_deg[e] = 0;
}

// ================= gather: warp per node -> H cols [256,544) ===============
__global__ void gather_kernel(const float* __restrict__ edge_attr) {
    const int warp_g = (blockIdx.x * blockDim.x + threadIdx.x) >> 5;
    if (warp_g >= N_NODES) return;
    const int lane = threadIdx.x & 31;
    const int beg = g_off[warp_g];
    const int end = g_off[warp_g + 1];

    float s0 = 0.f, s1 = 0.f, s2 = 0.f;
    float m0 = -__int_as_float(0x7F800000), m1 = m0, m2 = m0;

    for (int i = beg; i < end; i++) {
        const int e = g_bin[i];
        const float* row = edge_attr + (size_t)e * EDGE_F;
        float v0 = row[lane];
        float v1 = row[lane + 32];
        float v2 = row[lane + 64];
        s0 += v0; s1 += v1; s2 += v2;
        m0 = fmaxf(m0, v0); m1 = fmaxf(m1, v1); m2 = fmaxf(m2, v2);
    }
    const int cnt = end - beg;
    if (cnt == 0) { m0 = 0.f; m1 = 0.f; m2 = 0.f; }
    const float inv = 1.0f / (float)max(cnt, 1);

    __half* H = g_H + (size_t)warp_g * KH;
    H[256 + lane] = __float2half_rn(s0);
    H[288 + lane] = __float2half_rn(s1);
    H[320 + lane] = __float2half_rn(s2);
    H[352 + lane] = __float2half_rn(m0);
    H[384 + lane] = __float2half_rn(m1);
    H[416 + lane] = __float2half_rn(m2);
    H[448 + lane] = __float2half_rn(s0 * inv);
    H[480 + lane] = __float2half_rn(s1 * inv);
    H[512 + lane] = __float2half_rn(s2 * inv);
}

// ================== plain fp16 GEMM on mma.sync ============================
// C[128,128]/CTA, 8 warps 2(M)x4(N), warp tile 64x32, KC=32, S=4, 2 CTAs/SM.
// Single __syncthreads per chunk: wait(S-2) -> sync -> issue loads -> compute.
// MODE 0: out = relu(acc + ub1[batch[row]][col]) -> fp16
// MODE 1: out = acc + bias[col] + resid -> f32
template<int K_TOTAL, int N_TOTAL, int MODE>
__global__ void __launch_bounds__(256, 2) hmma_gemm_kernel(
    const __half* __restrict__ A, const __half* __restrict__ B,
    const float* __restrict__ bias, const float* __restrict__ resid,
    const int* __restrict__ batchp,
    __half* __restrict__ outh, float* __restrict__ outf, int M)
{
    constexpr int KC = 32;
    constexpr int S  = 4;
    constexpr int TILE_B = 128 * 64;      // 8192
    constexpr int STAGE_B = 2 * TILE_B;   // A, B
    constexpr int NCH = K_TOTAL / KC;

    extern __shared__ char smem[];
    const uint32_t smem_u = smem_to_u32(smem);

    const int tid = threadIdx.x;
    const int lid = tid & 31;
    const int wid = tid >> 5;
    const int warp_m = wid & 1;
    const int warp_n = wid >> 1;
    const int blockN = blockIdx.x * 128;
    const int blockM = blockIdx.y * 128;

    float acc[64];
    #pragma unroll
    for (int i = 0; i < 64; i++) acc[i] = 0.0f;

    const int ldrow0 = tid >> 2;
    const int ldseg  = tid & 3;

    auto load_chunk = [&](int c) {
        if (c >= NCH) return;
        const int kb = c * KC;
        const uint32_t sb = smem_u + (uint32_t)(c % S) * STAGE_B;
        #pragma unroll
        for (int i = 0; i < 2; i++) {
            const int row = ldrow0 + 64 * i;
            const uint32_t doff = sw_off(row, ldseg);
            const int gr = blockM + row;
            const bool v = gr < M;
            const size_t goA = (size_t)(v ? gr : 0) * K_TOTAL + kb + ldseg * 8;
            cp16(sb + doff, A + goA, v);
            const size_t goB = (size_t)(blockN + row) * K_TOTAL + kb + ldseg * 8;
            cp16(sb + TILE_B + doff, B + goB, true);
        }
    };

    // prologue: stage chunks 0..S-2
    #pragma unroll
    for (int c = 0; c < S - 1; c++) {
        load_chunk(c);
        CP_COMMIT();
    }

    const int lr = lid & 15;
    const int lk = (lid >> 4) * 8;

    for (int c = 0; c < NCH; c++) {
        CP_WAIT(S - 2);          // chunk c's group complete
        __syncthreads();         // data visible; compute(c-1) finished by all
        load_chunk(c + S - 1);   // overwrites slot (c-1)%S — safe per sync
        CP_COMMIT();

        const uint32_t sb = smem_u + (uint32_t)(c % S) * STAGE_B;
        const uint32_t aT = sb, bT = sb + TILE_B;

        #pragma unroll
        for (int kk = 0; kk < KC; kk += 16) {
            const int kchunk = (kk + lk) >> 3;
            uint32_t bh[8];
            #pragma unroll
            for (int bn = 0; bn < 2; bn++) {
                const uint32_t off = sw_off(warp_n * 32 + bn * 16 + lr, kchunk);
                ldsm4(&bh[bn * 4], bT + off);
            }
            #pragma unroll
            for (int am = 0; am < 4; am++) {
                uint32_t ah[4];
                const uint32_t off = sw_off(warp_m * 64 + am * 16 + lr, kchunk);
                ldsm4(ah, aT + off);
                #pragma unroll
                for (int an = 0; an < 4; an++) {
                    const int bn = an >> 1, sel = an & 1;
                    float* d = &acc[(am * 4 + an) * 4];
                    mma16816(d, ah, bh[bn * 4 + sel], bh[bn * 4 + sel + 2]);
                }
            }
        }
    }

    const int g = lid >> 2;
    const int t = lid & 3;
    #pragma unroll
    for (int am = 0; am < 4; am++) {
        #pragma unroll
        for (int an = 0; an < 4; an++) {
            const float* d = &acc[(am * 4 + an) * 4];
            const int col = blockN + warp_n * 32 + an * 8 + 2 * t;
            #pragma unroll
            for (int half = 0; half < 2; half++) {
                const int row = blockM + warp_m * 64 + am * 16 + g + half * 8;
                if (row >= M) continue;
                float bia0, bia1;
                if (MODE == 0) {
                    const int gg = batchp[row];
                    bia0 = bias[gg * N_TOTAL + col];
                    bia1 = bias[gg * N_TOTAL + col + 1];
                } else {
                    bia0 = bias[col];
                    bia1 = bias[col + 1];
                }
                float v0 = d[half * 2 + 0] + bia0;
                float v1 = d[half * 2 + 1] + bia1;
                const size_t o = (size_t)row * N_TOTAL + col;
                if (MODE == 0) {
                    __half2 p(__float2half_rn(fmaxf(v0, 0.0f)),
                              __float2half_rn(fmaxf(v1, 0.0f)));
                    *reinterpret_cast<uint32_t*>(outh + o) = *reinterpret_cast<uint32_t*>(&p);
                } else {
                    float2 r;
                    r.x = v0 + resid[o];
                    r.y = v1 + resid[o + 1];
                    *reinterpret_cast<float2*>(outf + o) = r;
                }
            }
        }
    }
}

// ---------------- launch ----------------
extern "C" void kernel_launch(void* const* d_in, const int* in_sizes, int n_in,
                              void* d_out, int out_size) {
    const float* x         = (const float*)d_in[0];
    const float* edge_attr = (const float*)d_in[1];
    const float* u         = (const float*)d_in[2];
    const float* W1        = (const float*)d_in[3];
    const float* b1        = (const float*)d_in[4];
    const float* W2        = (const float*)d_in[5];
    const float* b2        = (const float*)d_in[6];
    const int*   edge_index= (const int*)d_in[7];
    const int*   batch     = (const int*)d_in[8];
    float* out = (float*)d_out;

    const int* col = edge_index + N_EDGES;

    __half *pH, *pMid, *pW1, *pW2;
    float* pUb1;
    cudaGetSymbolAddress((void**)&pH,  g_H);
    cudaGetSymbolAddress((void**)&pMid, g_mid);
    cudaGetSymbolAddress((void**)&pW1, g_Wt1);
    cudaGetSymbolAddress((void**)&pW2, g_Wt2);
    cudaGetSymbolAddress((void**)&pUb1, g_ub1);

    const int SMEM_BYTES = 4 * 2 * 128 * 64;   // 65536
    cudaFuncSetAttribute(hmma_gemm_kernel<KH, HIDDEN, 0>,
                         cudaFuncAttributeMaxDynamicSharedMemorySize, SMEM_BYTES);
    cudaFuncSetAttribute(hmma_gemm_kernel<HIDDEN, NODE_F, 1>,
                         cudaFuncAttributeMaxDynamicSharedMemorySize, SMEM_BYTES);

    // 1) count (+ all CSR-independent prep, overlapped)
    count_prep_kernel<<<A_COUNT + A_REST + A_WT1 + A_WT2 + A_UB1, 256>>>(
        col, x, u, W1, b1, W2);
    // 2) scan
    scan_kernel<<<1, 1024>>>();
    // 3) fill (+ re-zero g_deg for next replay)
    fill_kernel<<<(N_EDGES + 255) / 256, 256>>>(col);
    // 4) gather
    gather_kernel<<<(N_NODES * 32 + 255) / 256, 256>>>(edge_attr);
    // 5) GEMM1: mid = relu(H @ W1[0:544] + ub1[batch])  [50000,1024]
    {
        dim3 grid(HIDDEN / 128, (N_NODES + 127) / 128);
        hmma_gemm_kernel<KH, HIDDEN, 0><<<grid, 256, SMEM_BYTES>>>(
            pH, pW1, pUb1, nullptr, batch, pMid, nullptr, N_NODES);
    }
    // 6) GEMM2: out = mid @ W2 + b2 + x  [50000,256]
    {
        dim3 grid(NODE_F / 128, (N_NODES + 127) / 128);
        hmma_gemm_kernel<HIDDEN, NODE_F, 1><<<grid, 256, SMEM_BYTES>>>(
            pMid, pW2, b2, x, nullptr, nullptr, out, N_NODES);
    }
}

// round 16
// speedup vs baseline: 2.6852x; 1.0182x over previous
#include <cuda_runtime.h>
#include <cuda_fp16.h>
#include <stdint.h>

#define N_NODES 50000
#define N_EDGES 800000
#define EDGE_F  96
#define NODE_F  256
#define GLOB_F  64
#define HIDDEN  1024
#define MLP_IN  608
#define KH      544   // GEMM1 K: x(256) + sum/max/mean(288); u folded into bias table

// ---------------- scratch (device globals: allocation-free) ----------------
__device__ alignas(16) int g_deg[N_NODES];   // zero at load; fill_kernel re-zeros
__device__ alignas(16) int g_off[N_NODES + 4];
__device__ alignas(16) int g_cur[N_NODES];
__device__ int g_bin[N_EDGES];
__device__ float g_ub1[8 * HIDDEN];   // per-graph bias: b1 + u[g] @ W1[544:608]
// fp16 operands (both sides rounded; 10-bit mantissa == tf32 accuracy class)
__device__ alignas(16) __half g_H[(size_t)N_NODES * KH];
__device__ alignas(16) __half g_mid[(size_t)N_NODES * HIDDEN];
__device__ alignas(16) __half g_Wt1[(size_t)HIDDEN * KH];      // [n][k]
__device__ alignas(16) __half g_Wt2[(size_t)NODE_F * HIDDEN];  // [n][k]

// ======================= helpers ===========================================
__device__ __forceinline__ uint32_t smem_to_u32(const void* p) {
    uint32_t a;
    asm("{ .reg .u64 t; cvta.to.shared.u64 t, %1; cvt.u32.u64 %0, t; }"
        : "=r"(a) : "l"(p));
    return a;
}

__device__ __forceinline__ void cp16(uint32_t dst, const void* src, bool valid) {
    asm volatile("cp.async.cg.shared.global [%0], [%1], 16, %2;"
                 :: "r"(dst), "l"(src), "r"(valid ? 16 : 0));
}
#define CP_COMMIT() asm volatile("cp.async.commit_group;" ::: "memory")
#define CP_WAIT(n)  asm volatile("cp.async.wait_group %0;" :: "n"(n) : "memory")

__device__ __forceinline__ void ldsm4(uint32_t* r, uint32_t addr) {
    asm volatile("ldmatrix.sync.aligned.m8n8.x4.shared.b16 {%0,%1,%2,%3}, [%4];"
                 : "=r"(r[0]), "=r"(r[1]), "=r"(r[2]), "=r"(r[3]) : "r"(addr));
}

// fp16 mma with f32 accumulate: D[16x8] += A[16x16] * B[16x8]
__device__ __forceinline__ void mma16816(float* d, const uint32_t* a,
                                         uint32_t b0, uint32_t b1) {
    asm volatile(
        "mma.sync.aligned.m16n8k16.row.col.f32.f16.f16.f32 "
        "{%0,%1,%2,%3}, {%4,%5,%6,%7}, {%8,%9}, {%0,%1,%2,%3};"
        : "+f"(d[0]), "+f"(d[1]), "+f"(d[2]), "+f"(d[3])
        : "r"(a[0]), "r"(a[1]), "r"(a[2]), "r"(a[3]), "r"(b0), "r"(b1));
}

// 64B-row smem tile with XOR swizzle (conflict-free for 8-lane ldmatrix phases)
__device__ __forceinline__ uint32_t sw_off(int row, int chunk) {
    return (uint32_t)row * 64u + (uint32_t)((chunk ^ ((row >> 1) & 3)) << 4);
}

// ===================== CSR: count -> scan -> fill ==========================
__global__ void count_kernel(const int* __restrict__ col) {
    int e = blockIdx.x * blockDim.x + threadIdx.x;
    if (e < N_EDGES) atomicAdd(&g_deg[col[e]], 1);
}

// single-CTA chunked exclusive scan, 4 elems/thread, int4 I/O
__global__ void scan_kernel() {
    __shared__ int warp_sums[32];
    __shared__ int carry_s;
    const int tid = threadIdx.x;
    const int lane = tid & 31, wid = tid >> 5;
    if (tid == 0) carry_s = 0;
    __syncthreads();
    for (int base = 0; base < N_NODES; base += 4096) {
        const int i = base + tid * 4;
        int4 v = make_int4(0, 0, 0, 0);
        if (i < N_NODES)  // N_NODES % 4 == 0 -> full vector in bounds
            v = *reinterpret_cast<const int4*>(g_deg + i);
        const int s = v.x + v.y + v.z + v.w;
        int xval = s;
        #pragma unroll
        for (int o = 1; o < 32; o <<= 1) {
            int y = __shfl_up_sync(0xFFFFFFFFu, xval, o);
            if (lane >= o) xval += y;
        }
        if (lane == 31) warp_sums[wid] = xval;
        __syncthreads();
        if (wid == 0) {
            int w = warp_sums[lane];
            #pragma unroll
            for (int o = 1; o < 32; o <<= 1) {
                int y = __shfl_up_sync(0xFFFFFFFFu, w, o);
                if (lane >= o) w += y;
            }
            warp_sums[lane] = w;
        }
        __syncthreads();
        const int excl = xval - s + (wid > 0 ? warp_sums[wid - 1] : 0) + carry_s;
        if (i < N_NODES) {
            int4 e;
            e.x = excl;
            e.y = e.x + v.x;
            e.z = e.y + v.y;
            e.w = e.z + v.z;
            *reinterpret_cast<int4*>(g_off + i) = e;
            *reinterpret_cast<int4*>(g_cur + i) = e;
        }
        __syncthreads();
        if (tid == 0) carry_s += warp_sums[31];
        __syncthreads();
    }
    if (tid == 0) g_off[N_NODES] = N_EDGES;
}

// fill bins; also re-zero g_deg so the next replay starts clean (deterministic)
__global__ void fill_kernel(const int* __restrict__ col) {
    int e = blockIdx.x * blockDim.x + threadIdx.x;
    if (e < N_EDGES) {
        int pos = atomicAdd(&g_cur[col[e]], 1);
        g_bin[pos] = e;
    }
    if (e < N_NODES) g_deg[e] = 0;
}

// ====== merged gather + CSR-independent prep (concurrent, DRAM-bound) ======
#define G_GATHER 6250                          // 50000 warps, 8/block
#define G_REST   12500                         // 50000*256/4 /256
#define G_WT1    (HIDDEN * (KH / 4) / 256)     // 544
#define G_WT2    (NODE_F * (HIDDEN / 4) / 256) // 256
#define G_UB1    32

__global__ void gather_prep_kernel(const float* __restrict__ edge_attr,
                                   const float* __restrict__ x,
                                   const float* __restrict__ u,
                                   const float* __restrict__ W1,
                                   const float* __restrict__ b1,
                                   const float* __restrict__ W2) {
    const int b = blockIdx.x;
    if (b < G_GATHER) {
        // ---- gather: warp per node -> H cols [256,544), 4-edge unroll ----
        const int warp_g = (b * 256 + (int)threadIdx.x) >> 5;
        if (warp_g >= N_NODES) return;
        const int lane = threadIdx.x & 31;
        const int beg = g_off[warp_g];
        const int end = g_off[warp_g + 1];

        float s0 = 0.f, s1 = 0.f, s2 = 0.f;
        float m0 = -__int_as_float(0x7F800000), m1 = m0, m2 = m0;

        int i = beg;
        for (; i + 4 <= end; i += 4) {
            const int e0 = g_bin[i],     e1 = g_bin[i + 1];
            const int e2 = g_bin[i + 2], e3 = g_bin[i + 3];
            const float* r0 = edge_attr + (size_t)e0 * EDGE_F;
            const float* r1 = edge_attr + (size_t)e1 * EDGE_F;
            const float* r2 = edge_attr + (size_t)e2 * EDGE_F;
            const float* r3 = edge_attr + (size_t)e3 * EDGE_F;
            float a0 = r0[lane], a1 = r0[lane + 32], a2 = r0[lane + 64];
            float b0 = r1[lane], b1v = r1[lane + 32], b2 = r1[lane + 64];
            float c0 = r2[lane], c1 = r2[lane + 32], c2 = r2[lane + 64];
            float d0 = r3[lane], d1 = r3[lane + 32], d2 = r3[lane + 64];
            s0 += (a0 + b0) + (c0 + d0);
            s1 += (a1 + b1v) + (c1 + d1);
            s2 += (a2 + b2) + (c2 + d2);
            m0 = fmaxf(m0, fmaxf(fmaxf(a0, b0), fmaxf(c0, d0)));
            m1 = fmaxf(m1, fmaxf(fmaxf(a1, b1v), fmaxf(c1, d1)));
            m2 = fmaxf(m2, fmaxf(fmaxf(a2, b2), fmaxf(c2, d2)));
        }
        for (; i < end; i++) {
            const int e = g_bin[i];
            const float* row = edge_attr + (size_t)e * EDGE_F;
            float v0 = row[lane], v1 = row[lane + 32], v2 = row[lane + 64];
            s0 += v0; s1 += v1; s2 += v2;
            m0 = fmaxf(m0, v0); m1 = fmaxf(m1, v1); m2 = fmaxf(m2, v2);
        }
        const int cnt = end - beg;
        if (cnt == 0) { m0 = 0.f; m1 = 0.f; m2 = 0.f; }
        const float inv = 1.0f / (float)max(cnt, 1);

        __half* H = g_H + (size_t)warp_g * KH;
        H[256 + lane] = __float2half_rn(s0);
        H[288 + lane] = __float2half_rn(s1);
        H[320 + lane] = __float2half_rn(s2);
        H[352 + lane] = __float2half_rn(m0);
        H[384 + lane] = __float2half_rn(m1);
        H[416 + lane] = __float2half_rn(m2);
        H[448 + lane] = __float2half_rn(s0 * inv);
        H[480 + lane] = __float2half_rn(s1 * inv);
        H[512 + lane] = __float2half_rn(s2 * inv);
    } else if (b < G_GATHER + G_REST) {
        // ---- H cols [0,256) = fp16(x), x4 ----
        const int t = (b - G_GATHER) * 256 + (int)threadIdx.x;
        const int n = t >> 6;
        const int c = (t & 63) * 4;
        if (n >= N_NODES) return;
        const float4 v = *reinterpret_cast<const float4*>(x + (size_t)n * NODE_F + c);
        const size_t o = (size_t)n * KH + c;
        __half2 p0(__float2half_rn(v.x), __float2half_rn(v.y));
        __half2 p1(__float2half_rn(v.z), __float2half_rn(v.w));
        reinterpret_cast<__half2*>(g_H + o)[0] = p0;
        reinterpret_cast<__half2*>(g_H + o)[1] = p1;
    } else if (b < G_GATHER + G_REST + G_WT1) {
        // ---- Wt1[n][k] = fp16(W1[k][n]), k in [0,544) ----
        const int t = (b - G_GATHER - G_REST) * 256 + (int)threadIdx.x;
        const int n = t / (KH / 4);
        const int k = (t % (KH / 4)) * 4;
        const size_t o = (size_t)n * KH + k;
        __half2 p0(__float2half_rn(W1[(size_t)(k + 0) * HIDDEN + n]),
                   __float2half_rn(W1[(size_t)(k + 1) * HIDDEN + n]));
        __half2 p1(__float2half_rn(W1[(size_t)(k + 2) * HIDDEN + n]),
                   __float2half_rn(W1[(size_t)(k + 3) * HIDDEN + n]));
        reinterpret_cast<__half2*>(g_Wt1 + o)[0] = p0;
        reinterpret_cast<__half2*>(g_Wt1 + o)[1] = p1;
    } else if (b < G_GATHER + G_REST + G_WT1 + G_WT2) {
        // ---- Wt2[n][k] = fp16(W2[k][n]) ----
        const int t = (b - G_GATHER - G_REST - G_WT1) * 256 + (int)threadIdx.x;
        const int n = t / (HIDDEN / 4);
        const int k = (t % (HIDDEN / 4)) * 4;
        const size_t o = (size_t)n * HIDDEN + k;
        __half2 p0(__float2half_rn(W2[(size_t)(k + 0) * NODE_F + n]),
                   __float2half_rn(W2[(size_t)(k + 1) * NODE_F + n]));
        __half2 p1(__float2half_rn(W2[(size_t)(k + 2) * NODE_F + n]),
                   __float2half_rn(W2[(size_t)(k + 3) * NODE_F + n]));
        reinterpret_cast<__half2*>(g_Wt2 + o)[0] = p0;
        reinterpret_cast<__half2*>(g_Wt2 + o)[1] = p1;
    } else {
        // ---- ub1[g][n] = b1[n] + sum_k u[g,k] * W1[544+k][n]  (full f32) ----
        const int t = (b - G_GATHER - G_REST - G_WT1 - G_WT2) * 256 + (int)threadIdx.x;
        const int g = t >> 10;
        const int n = t & 1023;
        if (g >= 8) return;
        float s = b1[n];
        #pragma unroll 8
        for (int k = 0; k < GLOB_F; k++)
            s = fmaf(u[g * GLOB_F + k], W1[(size_t)(KH + k) * HIDDEN + n], s);
        g_ub1[g * HIDDEN + n] = s;
    }
}

// ================== plain fp16 GEMM on mma.sync ============================
// C[128,128]/CTA, 8 warps 2(M)x4(N), warp tile 64x32, KC=32, S=4, 2 CTAs/SM.
// Single __syncthreads per chunk: wait(S-2) -> sync -> issue loads -> compute.
// MODE 0: out = relu(acc + ub1[batch[row]][col]) -> fp16
// MODE 1: out = acc + bias[col] + resid -> f32
template<int K_TOTAL, int N_TOTAL, int MODE>
__global__ void __launch_bounds__(256, 2) hmma_gemm_kernel(
    const __half* __restrict__ A, const __half* __restrict__ B,
    const float* __restrict__ bias, const float* __restrict__ resid,
    const int* __restrict__ batchp,
    __half* __restrict__ outh, float* __restrict__ outf, int M)
{
    constexpr int KC = 32;
    constexpr int S  = 4;
    constexpr int TILE_B = 128 * 64;      // 8192
    constexpr int STAGE_B = 2 * TILE_B;   // A, B
    constexpr int NCH = K_TOTAL / KC;

    extern __shared__ char smem[];
    const uint32_t smem_u = smem_to_u32(smem);

    const int tid = threadIdx.x;
    const int lid = tid & 31;
    const int wid = tid >> 5;
    const int warp_m = wid & 1;
    const int warp_n = wid >> 1;
    const int blockN = blockIdx.x * 128;
    const int blockM = blockIdx.y * 128;

    float acc[64];
    #pragma unroll
    for (int i = 0; i < 64; i++) acc[i] = 0.0f;

    const int ldrow0 = tid >> 2;
    const int ldseg  = tid & 3;

    auto load_chunk = [&](int c) {
        if (c >= NCH) return;
        const int kb = c * KC;
        const uint32_t sb = smem_u + (uint32_t)(c % S) * STAGE_B;
        #pragma unroll
        for (int i = 0; i < 2; i++) {
            const int row = ldrow0 + 64 * i;
            const uint32_t doff = sw_off(row, ldseg);
            const int gr = blockM + row;
            const bool v = gr < M;
            const size_t goA = (size_t)(v ? gr : 0) * K_TOTAL + kb + ldseg * 8;
            cp16(sb + doff, A + goA, v);
            const size_t goB = (size_t)(blockN + row) * K_TOTAL + kb + ldseg * 8;
            cp16(sb + TILE_B + doff, B + goB, true);
        }
    };

    // prologue: stage chunks 0..S-2
    #pragma unroll
    for (int c = 0; c < S - 1; c++) {
        load_chunk(c);
        CP_COMMIT();
    }

    const int lr = lid & 15;
    const int lk = (lid >> 4) * 8;

    for (int c = 0; c < NCH; c++) {
        CP_WAIT(S - 2);          // chunk c's group complete
        __syncthreads();         // data visible; compute(c-1) finished by all
        load_chunk(c + S - 1);   // overwrites slot (c-1)%S — safe per sync
        CP_COMMIT();

        const uint32_t sb = smem_u + (uint32_t)(c % S) * STAGE_B;
        const uint32_t aT = sb, bT = sb + TILE_B;

        #pragma unroll
        for (int kk = 0; kk < KC; kk += 16) {
            const int kchunk = (kk + lk) >> 3;
            uint32_t bh[8];
            #pragma unroll
            for (int bn = 0; bn < 2; bn++) {
                const uint32_t off = sw_off(warp_n * 32 + bn * 16 + lr, kchunk);
                ldsm4(&bh[bn * 4], bT + off);
            }
            #pragma unroll
            for (int am = 0; am < 4; am++) {
                uint32_t ah[4];
                const uint32_t off = sw_off(warp_m * 64 + am * 16 + lr, kchunk);
                ldsm4(ah, aT + off);
                #pragma unroll
                for (int an = 0; an < 4; an++) {
                    const int bn = an >> 1, sel = an & 1;
                    float* d = &acc[(am * 4 + an) * 4];
                    mma16816(d, ah, bh[bn * 4 + sel], bh[bn * 4 + sel + 2]);
                }
            }
        }
    }

    const int g = lid >> 2;
    const int t = lid & 3;
    #pragma unroll
    for (int am = 0; am < 4; am++) {
        #pragma unroll
        for (int an = 0; an < 4; an++) {
            const float* d = &acc[(am * 4 + an) * 4];
            const int col = blockN + warp_n * 32 + an * 8 + 2 * t;
            #pragma unroll
            for (int half = 0; half < 2; half++) {
                const int row = blockM + warp_m * 64 + am * 16 + g + half * 8;
                if (row >= M) continue;
                float bia0, bia1;
                if (MODE == 0) {
                    const int gg = batchp[row];
                    bia0 = bias[gg * N_TOTAL + col];
                    bia1 = bias[gg * N_TOTAL + col + 1];
                } else {
                    bia0 = bias[col];
                    bia1 = bias[col + 1];
                }
                float v0 = d[half * 2 + 0] + bia0;
                float v1 = d[half * 2 + 1] + bia1;
                const size_t o = (size_t)row * N_TOTAL + col;
                if (MODE == 0) {
                    __half2 p(__float2half_rn(fmaxf(v0, 0.0f)),
                              __float2half_rn(fmaxf(v1, 0.0f)));
                    *reinterpret_cast<uint32_t*>(outh + o) = *reinterpret_cast<uint32_t*>(&p);
                } else {
                    float2 r;
                    r.x = v0 + resid[o];
                    r.y = v1 + resid[o + 1];
                    *reinterpret_cast<float2*>(outf + o) = r;
                }
            }
        }
    }
}

// ---------------- launch ----------------
extern "C" void kernel_launch(void* const* d_in, const int* in_sizes, int n_in,
                              void* d_out, int out_size) {
    const float* x         = (const float*)d_in[0];
    const float* edge_attr = (const float*)d_in[1];
    const float* u         = (const float*)d_in[2];
    const float* W1        = (const float*)d_in[3];
    const float* b1        = (const float*)d_in[4];
    const float* W2        = (const float*)d_in[5];
    const float* b2        = (const float*)d_in[6];
    const int*   edge_index= (const int*)d_in[7];
    const int*   batch     = (const int*)d_in[8];
    float* out = (float*)d_out;

    const int* col = edge_index + N_EDGES;

    __half *pH, *pMid, *pW1, *pW2;
    float* pUb1;
    cudaGetSymbolAddress((void**)&pH,  g_H);
    cudaGetSymbolAddress((void**)&pMid, g_mid);
    cudaGetSymbolAddress((void**)&pW1, g_Wt1);
    cudaGetSymbolAddress((void**)&pW2, g_Wt2);
    cudaGetSymbolAddress((void**)&pUb1, g_ub1);

    const int SMEM_BYTES = 4 * 2 * 128 * 64;   // 65536
    cudaFuncSetAttribute(hmma_gemm_kernel<KH, HIDDEN, 0>,
                         cudaFuncAttributeMaxDynamicSharedMemorySize, SMEM_BYTES);
    cudaFuncSetAttribute(hmma_gemm_kernel<HIDDEN, NODE_F, 1>,
                         cudaFuncAttributeMaxDynamicSharedMemorySize, SMEM_BYTES);

    // 1) count
    count_kernel<<<(N_EDGES + 255) / 256, 256>>>(col);
    // 2) scan
    scan_kernel<<<1, 1024>>>();
    // 3) fill (+ re-zero g_deg for next replay)
    fill_kernel<<<(N_EDGES + 255) / 256, 256>>>(col);
    // 4) gather + all CSR-independent prep (concurrent, DRAM-bound)
    gather_prep_kernel<<<G_GATHER + G_REST + G_WT1 + G_WT2 + G_UB1, 256>>>(
        edge_attr, x, u, W1, b1, W2);
    // 5) GEMM1: mid = relu(H @ W1[0:544] + ub1[batch])  [50000,1024]
    {
        dim3 grid(HIDDEN / 128, (N_NODES + 127) / 128);
        hmma_gemm_kernel<KH, HIDDEN, 0><<<grid, 256, SMEM_BYTES>>>(
            pH, pW1, pUb1, nullptr, batch, pMid, nullptr, N_NODES);
    }
    // 6) GEMM2: out = mid @ W2 + b2 + x  [50000,256]
    {
        dim3 grid(NODE_F / 128, (N_NODES + 127) / 128);
        hmma_gemm_kernel<HIDDEN, NODE_F, 1><<<grid, 256, SMEM_BYTES>>>(
            pMid, pW2, b2, x, nullptr, nullptr, out, N_NODES);
    }
}